// round 15
// baseline (speedup 1.0000x reference)
#include <cuda_runtime.h>
#include <cuda_bf16.h>
#include <cuda_fp16.h>
#include <math.h>

static constexpr int B_ = 2, N_ = 4096, C_ = 128, K_ = 16, P_ = 43, CLS_ = 16, F_ = 512;
static constexpr int M_ = B_ * N_;
static constexpr int PC_ = P_ * C_;          // 5504
static constexpr float R2_ = 0.01f;          // RADIUS^2
static constexpr float INV_SIG_ = 10.0f;     // 1/RADIUS

// ---------------- static device scratch ----------------
__device__ float4 g_xyzw[M_];
__device__ int    g_nbr[M_ * K_];
__device__ float  g_kpts[P_ * 3];
__device__ float  g_f[M_ * C_];
__device__ float  g_x0[M_ * C_];
__device__ __half g_fk_h[(size_t)M_ * PC_];                 // 90 MB, single fp16
__device__ __half g_wT1_h[(size_t)C_ * PC_];
__device__ __half g_wT2_h[(size_t)C_ * PC_];
__device__ __half g_wak_h[C_ * C_];
__device__ __half g_wav_h[C_ * C_];
__device__ __half g_war_h[C_ * C_];
__device__ __half g_wao_h[C_ * C_];
__device__ __half g_wfk_h[F_ * C_];
__device__ __half g_wfr_h[C_ * C_];
__device__ __half g_wfv_h[C_ * F_];
__device__ float g_pts[M_ * C_];
__device__ float g_xn[M_ * C_];
__device__ float g_rr[M_ * C_];
__device__ float g_kT[M_ * C_];
__device__ float g_vT[M_ * C_];
__device__ float g_wkv[M_ * C_];
__device__ float g_ffn[M_ * F_];
__device__ float g_p1[256 * C_];
__device__ float g_p2[256 * C_];
__device__ float g_bnA[C_];
__device__ float g_bnB[C_];

// ---------------- helpers ----------------
__device__ __forceinline__ unsigned smem_u32(const void* p) {
    unsigned a;
    asm("{ .reg .u64 t; cvta.to.shared.u64 t, %1; cvt.u32.u64 %0, t; }" : "=r"(a) : "l"(p));
    return a;
}
__device__ __forceinline__ void cp16(void* dst, const void* src) {
    unsigned d;
    asm("{ .reg .u64 t; cvta.to.shared.u64 t, %1; cvt.u32.u64 %0, t; }" : "=r"(d) : "l"(dst));
    asm volatile("cp.async.cg.shared.global [%0], [%1], 16;" :: "r"(d), "l"(src));
}
__device__ __forceinline__ void cp_commit() {
    asm volatile("cp.async.commit_group;" ::: "memory");
}
template <int N>
__device__ __forceinline__ void cp_wait() {
    asm volatile("cp.async.wait_group %0;" :: "n"(N) : "memory");
}
__device__ __forceinline__ void mma16816h(float* c, const unsigned* a, const unsigned* b) {
    asm volatile(
        "mma.sync.aligned.m16n8k16.row.col.f32.f16.f16.f32 "
        "{%0,%1,%2,%3}, {%4,%5,%6,%7}, {%8,%9}, {%0,%1,%2,%3};"
        : "+f"(c[0]), "+f"(c[1]), "+f"(c[2]), "+f"(c[3])
        : "r"(a[0]), "r"(a[1]), "r"(a[2]), "r"(a[3]), "r"(b[0]), "r"(b[1]));
}
__device__ __forceinline__ void ldsm4(unsigned* r, unsigned a) {
    asm volatile("ldmatrix.sync.aligned.m8n8.x4.shared.b16 {%0,%1,%2,%3}, [%4];"
        : "=r"(r[0]), "=r"(r[1]), "=r"(r[2]), "=r"(r[3]) : "r"(a));
}
__device__ __forceinline__ unsigned pack_h2(float a, float b) {
    __half2 h;
    h.x = __float2half(a); h.y = __float2half(b);
    return *reinterpret_cast<unsigned*>(&h);
}
// packed fp32 FMA (Blackwell): c = a * b + c, per-lane full fp32
__device__ __forceinline__ void fma2(unsigned long long& c, unsigned long long a,
                                     unsigned long long b) {
    asm("fma.rn.f32x2 %0, %1, %2, %0;" : "+l"(c) : "l"(a), "l"(b));
}

// ---------------- setup part 1: kpts + xyz ----------------
__global__ void __launch_bounds__(256) k_setup_geo(const float* __restrict__ p) {
    int bid = blockIdx.x;
    int tid = threadIdx.x;
    if (bid == 0) {
        int t = tid;
        if (t < P_) {
            double x = 0.0, y = 0.0, z = 0.0;
            if (t > 0) {
                int mc = (t <= 14) ? 14 : 28;
                double scale = (t <= 14) ? 0.05 : 0.1;
                int i0 = (t <= 14) ? (t - 1) : (t - 15);
                double i = i0 + 0.5;
                double phi = acos(1.0 - 2.0 * i / (double)mc);
                double theta = 3.141592653589793 * (1.0 + sqrt(5.0)) * i;
                x = cos(theta) * sin(phi) * scale;
                y = sin(theta) * sin(phi) * scale;
                z = cos(phi) * scale;
            }
            g_kpts[t * 3 + 0] = (float)x;
            g_kpts[t * 3 + 1] = (float)y;
            g_kpts[t * 3 + 2] = (float)z;
        }
    } else {
        int m = (bid - 1) * 256 + tid;
        int b = m / N_, n = m - b * N_;
        float x = p[((size_t)b * 3 + 0) * N_ + n];
        float y = p[((size_t)b * 3 + 1) * N_ + n];
        float z = p[((size_t)b * 3 + 2) * N_ + n];
        g_xyzw[m] = make_float4(x, y, z, fmaf(x, x, fmaf(y, y, z * z)));
    }
}

// ---------------- setup part 2: all weight transposes (fp16) ----------------
__global__ void __launch_bounds__(256) k_setup_w(
    const float* __restrict__ kp1, const float* __restrict__ kp2,
    const float* __restrict__ awk, const float* __restrict__ awv,
    const float* __restrict__ awr, const float* __restrict__ awo,
    const float* __restrict__ fwk, const float* __restrict__ fwr,
    const float* __restrict__ fwv)
{
    int bid = blockIdx.x;
    int tid = threadIdx.x;
    const float* src; __half* hi; int Kd, Nd, lt;
    if (bid < 688)       { src = kp1; hi = g_wT1_h; Kd = PC_; Nd = C_; lt = bid; }
    else if (bid < 1376) { src = kp2; hi = g_wT2_h; Kd = PC_; Nd = C_; lt = bid - 688; }
    else if (bid < 1392) { src = awk; hi = g_wak_h; Kd = C_; Nd = C_; lt = bid - 1376; }
    else if (bid < 1408) { src = awv; hi = g_wav_h; Kd = C_; Nd = C_; lt = bid - 1392; }
    else if (bid < 1424) { src = awr; hi = g_war_h; Kd = C_; Nd = C_; lt = bid - 1408; }
    else if (bid < 1440) { src = awo; hi = g_wao_h; Kd = C_; Nd = C_; lt = bid - 1424; }
    else if (bid < 1504) { src = fwk; hi = g_wfk_h; Kd = C_; Nd = F_; lt = bid - 1440; }
    else if (bid < 1520) { src = fwr; hi = g_wfr_h; Kd = C_; Nd = C_; lt = bid - 1504; }
    else                 { src = fwv; hi = g_wfv_h; Kd = F_; Nd = C_; lt = bid - 1520; }
    int tn = Nd / 32;
    int kt = lt / tn, nt = lt - kt * tn;
    int k0 = kt * 32, n0 = nt * 32;
    __shared__ float sm[32][33];
    int tx = tid & 31, ty = tid >> 5;
    for (int i = ty; i < 32; i += 8)
        sm[i][tx] = src[(size_t)(k0 + i) * Nd + n0 + tx];
    __syncthreads();
    for (int i = ty; i < 32; i += 8)
        hi[(size_t)(n0 + i) * Kd + k0 + tx] = __float2half(sm[tx][i]);
}

// ---------------- knn (blocks 0..1023) + feature transpose (1024..2047) ----------------
__global__ void __launch_bounds__(256) k_knn_prep(const float* __restrict__ x) {
    __shared__ float4 tile[1024];
    int tid = threadIdx.x;
    if (blockIdx.x >= 1024) {
        float (*sm)[33] = reinterpret_cast<float(*)[33]>(tile);
        int pb = blockIdx.x - 1024;
        int c0 = (pb & 3) * 32, n0 = ((pb >> 2) & 127) * 32, b = pb >> 9;
        int tx = tid & 31, ty = tid >> 5;
        for (int i = ty; i < 32; i += 8)
            sm[i][tx] = x[((size_t)(b * C_ + c0 + i)) * N_ + n0 + tx];
        __syncthreads();
        for (int i = ty; i < 32; i += 8) {
            float v = sm[tx][i];
            size_t o = ((size_t)(b * N_ + n0 + i)) * C_ + c0 + tx;
            g_f[o] = v;
            g_x0[o] = v;
        }
        return;
    }
    int wid = tid >> 5, lane = tid & 31;
    int m = blockIdx.x * 8 + wid;
    int base = (m >> 12) * N_;
    float4 q = g_xyzw[m];
    float bd[K_]; int bi[K_];
#pragma unroll
    for (int k = 0; k < K_; k++) { bd[k] = 3.4e38f; bi[k] = 0x7FFFFFFF; }
    for (int t0 = 0; t0 < N_; t0 += 1024) {
        __syncthreads();
        for (int j = tid; j < 1024; j += 256) tile[j] = g_xyzw[base + t0 + j];
        __syncthreads();
#pragma unroll 2
        for (int t = 0; t < 32; t++) {
            int j = t * 32 + lane;
            float4 c = tile[j];
            float dot = fmaf(q.x, c.x, fmaf(q.y, c.y, q.z * c.z));
            float d2 = q.w + c.w - 2.0f * dot;
            if (d2 <= R2_ && d2 < bd[K_ - 1]) {
                int idx = t0 + j;
#pragma unroll
                for (int k = K_ - 1; k >= 0; k--) {
                    float pd = (k > 0) ? bd[k - 1] : -1.0f;
                    if (pd > d2) {
                        if (k > 0) { bd[k] = bd[k - 1]; bi[k] = bi[k - 1]; }
                    } else if (bd[k] > d2) {
                        bd[k] = d2; bi[k] = idx;
                    }
                }
            }
        }
    }
    float outd = 3.4e38f; int outi = 0x7FFFFFFF;
    for (int r = 0; r < K_; r++) {
        unsigned fb = __float_as_uint(bd[0]);
        fb = (fb & 0x80000000u) ? ~fb : (fb | 0x80000000u);
        unsigned long long key = (((unsigned long long)fb) << 32) | (unsigned)bi[0];
        unsigned long long kmin = key;
#pragma unroll
        for (int off = 16; off >= 1; off >>= 1) {
            unsigned long long o = __shfl_xor_sync(0xffffffffu, kmin, off);
            if (o < kmin) kmin = o;
        }
        if (key == kmin) {
#pragma unroll
            for (int k = 0; k < K_ - 1; k++) { bd[k] = bd[k + 1]; bi[k] = bi[k + 1]; }
            bd[K_ - 1] = 3.4e38f; bi[K_ - 1] = 0x7FFFFFFF;
        }
        if (lane == r) {
            unsigned tu = (unsigned)(kmin >> 32);
            unsigned ob = (tu & 0x80000000u) ? (tu ^ 0x80000000u) : ~tu;
            outd = __uint_as_float(ob);
            outi = (int)(unsigned)(kmin & 0xffffffffu);
        }
    }
    int wi0 = __shfl_sync(0xffffffffu, outi, 0);
    if (lane < K_) {
        int sel = (outd <= R2_) ? outi : wi0;
        g_nbr[m * K_ + lane] = base + sel;
    }
}

// ---------------- build fk (packed f32x2 FMA, single fp16 output) ----------------
__global__ void __launch_bounds__(128) k_build_fk(const float* __restrict__ fin) {
    int m0 = blockIdx.x * 2;
    int tid = threadIdx.x;
    int sub = tid >> 6, t = tid & 63, c0 = t * 2;
    __shared__ float2 infl[2][P_][K_];   // duplicated (w,w) pairs
    __shared__ float nx[2][K_], ny[2][K_], nz[2][K_];
    __shared__ int nidx[2][K_];
    if (tid < 2 * K_) {
        int ss = tid >> 4, kk = tid & 15;
        int nb = g_nbr[(m0 + ss) * K_ + kk];
        nidx[ss][kk] = nb;
        float4 nq = g_xyzw[nb];
        nx[ss][kk] = nq.x; ny[ss][kk] = nq.y; nz[ss][kk] = nq.z;
    }
    __syncthreads();
    for (int e = tid; e < 2 * P_ * K_; e += 128) {
        int ss = e / (P_ * K_);
        int rem = e - ss * P_ * K_;
        int pp = rem >> 4, k = rem & 15;
        float4 cq = g_xyzw[m0 + ss];
        float rx = nx[ss][k] - cq.x, ry = ny[ss][k] - cq.y, rz = nz[ss][k] - cq.z;
        float dx = rx - g_kpts[pp * 3], dy = ry - g_kpts[pp * 3 + 1], dz = rz - g_kpts[pp * 3 + 2];
        float d = sqrtf(fmaf(dx, dx, fmaf(dy, dy, dz * dz)) + 1e-12f);
        float w = fmaxf(0.0f, 1.0f - d * INV_SIG_);
        infl[ss][pp][k] = make_float2(w, w);
    }
    __syncthreads();
    unsigned long long Fv[K_];
#pragma unroll
    for (int k = 0; k < K_; k++)
        Fv[k] = *(const unsigned long long*)(fin + (size_t)nidx[sub][k] * C_ + c0);
    size_t dstb = (size_t)(m0 + sub) * PC_ + c0;
#pragma unroll 1
    for (int pp = 0; pp < P_; pp++) {
        unsigned long long acc = 0ull;   // packed (0.0f, 0.0f)
#pragma unroll
        for (int kk = 0; kk < 8; kk++) {
            float4 wv = *(const float4*)&infl[sub][pp][kk * 2];  // 2 dup pairs
            unsigned long long w0, w1;
            asm("mov.b64 %0, {%1, %2};" : "=l"(w0) : "f"(wv.x), "f"(wv.y));
            asm("mov.b64 %0, {%1, %2};" : "=l"(w1) : "f"(wv.z), "f"(wv.w));
            fma2(acc, w0, Fv[kk * 2]);
            fma2(acc, w1, Fv[kk * 2 + 1]);
        }
        float a0, a1;
        asm("mov.b64 {%0, %1}, %2;" : "=f"(a0), "=f"(a1) : "l"(acc));
        *reinterpret_cast<unsigned*>(g_fk_h + dstb + (size_t)pp * C_) = pack_h2(a0, a1);
    }
}

// ---------------- HMMA KPConv GEMM: split-K=2, fragment-pipelined, fp16 ----------------
static constexpr int GBK = 64;
static constexpr int HCH_ = (PC_ / GBK) / 2;             // 43 chunks per half
static constexpr int AP = 72;
static constexpr int ST_B  = 64 * AP * 2;                // 9216
static constexpr int ST_SZ = ST_B + 128 * AP * 2;        // 27648
static constexpr int SM_MMA = 3 * ST_SZ;                 // 82944

__global__ void __launch_bounds__(256) k_mma_kpconv(
    const __half* __restrict__ Bh,
    const float* __restrict__ Res, const float* __restrict__ Res2,
    float* __restrict__ Out0, float* __restrict__ Out1)
{
    extern __shared__ char smem[];
    unsigned sb = smem_u32(smem);
    int tid = threadIdx.x;
    int bm = blockIdx.x * 64;
    int half = blockIdx.y;
    int kbase = half * HCH_;
    int wid = tid >> 5, lane = tid & 31;
    int wm = wid & 1, wn = wid >> 1;
    int li = lane & 7, lm2 = lane >> 3;
    int a_m = (lm2 & 1) * 8 + li, a_k = (lm2 >> 1) * 8;
    int b_n = (lm2 >> 1) * 8 + li, b_k = (lm2 & 1) * 8;

    float acc[2][4][4];
#pragma unroll
    for (int i = 0; i < 2; i++)
#pragma unroll
        for (int j = 0; j < 4; j++)
#pragma unroll
            for (int q = 0; q < 4; q++) acc[i][j][q] = 0.f;

    auto load_chunk = [&](int ch, int s) {
        int k0 = ch * GBK;
        char* st = smem + s * ST_SZ;
#pragma unroll
        for (int i = 0; i < 2; i++) {
            int idx = tid + i * 256;
            int row = idx >> 3, seg = idx & 7;
            size_t srcoff = (size_t)(bm + row) * PC_ + k0 + seg * 8;
            cp16(st + (row * AP + seg * 8) * 2, g_fk_h + srcoff);
        }
#pragma unroll
        for (int i = 0; i < 4; i++) {
            int idx = tid + i * 256;
            int row = idx >> 3, seg = idx & 7;
            size_t srcoff = (size_t)row * PC_ + k0 + seg * 8;
            cp16(st + ST_B + (row * AP + seg * 8) * 2, Bh + srcoff);
        }
        cp_commit();
    };

    unsigned ah[2][2][4], bh[2][2][4];
    auto ldfrag = [&](int ks, int buf, unsigned stb) {
        int kb = ks * 16;
#pragma unroll
        for (int mt = 0; mt < 2; mt++)
            ldsm4(ah[buf][mt], stb + (((wm * 32 + mt * 16 + a_m) * AP) + kb + a_k) * 2);
#pragma unroll
        for (int np = 0; np < 2; np++)
            ldsm4(bh[buf][np], stb + ST_B + (((wn * 32 + np * 16 + b_n) * AP) + kb + b_k) * 2);
    };

    load_chunk(kbase + 0, 0);
    load_chunk(kbase + 1, 1);
    for (int ch = 0; ch < HCH_; ch++) {
        int s = ch % 3;
        if (ch + 2 < HCH_) { load_chunk(kbase + ch + 2, (ch + 2) % 3); cp_wait<2>(); }
        else if (ch + 1 < HCH_) cp_wait<1>();
        else cp_wait<0>();
        __syncthreads();
        unsigned stb = sb + s * ST_SZ;
        ldfrag(0, 0, stb);
#pragma unroll
        for (int ks = 0; ks < 4; ks++) {
            int cur = ks & 1;
            if (ks < 3) ldfrag(ks + 1, cur ^ 1, stb);
#pragma unroll
            for (int mt = 0; mt < 2; mt++)
#pragma unroll
                for (int nt = 0; nt < 4; nt++)
                    mma16816h(acc[mt][nt], ah[cur][mt], &bh[cur][nt >> 1][(nt & 1) * 2]);
        }
        __syncthreads();
    }

    int lr = lane >> 2;
    float* Out = half ? Out1 : Out0;
#pragma unroll
    for (int mt = 0; mt < 2; mt++) {
#pragma unroll
        for (int nt = 0; nt < 4; nt++) {
            int col = wn * 32 + nt * 8 + ((lane & 3) << 1);
#pragma unroll
            for (int h = 0; h < 2; h++) {
                int row = bm + wm * 32 + mt * 16 + lr + h * 8;
                size_t o = (size_t)row * C_ + col;
                float v0 = acc[mt][nt][h * 2 + 0];
                float v1 = acc[mt][nt][h * 2 + 1];
                if (half == 0) {
                    v0 += Res[o]; v1 += Res[o + 1];
                    if (Res2) { v0 += Res2[o]; v1 += Res2[o + 1]; }
                }
                *(float2*)(Out + o) = make_float2(v0, v1);
            }
        }
    }
}

// ---------------- combine split-K partials ----------------
__global__ void __launch_bounds__(256) k_add2(const float4* __restrict__ a,
                                              const float4* __restrict__ b,
                                              float4* __restrict__ o) {
    int i = blockIdx.x * 256 + threadIdx.x;
    float4 x = a[i], y = b[i];
    o[i] = make_float4(x.x + y.x, x.y + y.y, x.z + y.z, x.w + y.w);
}

// ---------------- batched HMMA small GEMM (single fp16, pipelined) ----------------
struct HA {
    const __half* bh;
    float* out; const float* mix; const float* Res; const float* Mul;
    int ep; int transN; int Nd;
};
struct HA3 { HA a[3]; };

static constexpr int HP = 40;
static constexpr int H_STG = 10240;
static constexpr int H_SZ = 2 * H_STG;

__global__ void __launch_bounds__(256) k_hgemm3(const float* __restrict__ A, HA3 args, int Kd) {
    HA h = args.a[blockIdx.z];
    int bn = blockIdx.y * 64;
    if (bn >= h.Nd) return;
    extern __shared__ char smem[];
    unsigned sb = smem_u32(smem);
    int tid = threadIdx.x;
    int bm = blockIdx.x * 64;
    int wid = tid >> 5, lane = tid & 31;
    int wm = wid & 3, wn = wid >> 2;
    int li = lane & 7, lm2 = lane >> 3;
    int a_m = (lm2 & 1) * 8 + li, a_k = (lm2 >> 1) * 8;
    int b_n = (lm2 >> 1) * 8 + li, b_k = (lm2 & 1) * 8;

    int arow = tid >> 2, akc = (tid & 3) * 8;
    int an = (bm + arow) & (N_ - 1);
    int brow = tid >> 2, bseg = tid & 3;

    float acc[4][4];
#pragma unroll
    for (int j = 0; j < 4; j++)
#pragma unroll
        for (int q = 0; q < 4; q++) acc[j][q] = 0.f;

    auto loadA = [&](int k0, float* f) {
        const float* ap = A + (size_t)(bm + arow) * Kd + k0 + akc;
        float4 v0 = *(const float4*)ap;
        float4 v1 = *(const float4*)(ap + 4);
        if (h.mix) {
            float4 p0 = make_float4(0.f, 0.f, 0.f, 0.f), p1 = p0;
            if (an != 0) {
                p0 = *(const float4*)(ap - Kd);
                p1 = *(const float4*)(ap - Kd + 4);
            }
            float4 m0 = *(const float4*)(h.mix + k0 + akc);
            float4 m1 = *(const float4*)(h.mix + k0 + akc + 4);
            v0.x = m0.x * v0.x + (1.f - m0.x) * p0.x;
            v0.y = m0.y * v0.y + (1.f - m0.y) * p0.y;
            v0.z = m0.z * v0.z + (1.f - m0.z) * p0.z;
            v0.w = m0.w * v0.w + (1.f - m0.w) * p0.w;
            v1.x = m1.x * v1.x + (1.f - m1.x) * p1.x;
            v1.y = m1.y * v1.y + (1.f - m1.y) * p1.y;
            v1.z = m1.z * v1.z + (1.f - m1.z) * p1.z;
            v1.w = m1.w * v1.w + (1.f - m1.w) * p1.w;
        }
        f[0] = v0.x; f[1] = v0.y; f[2] = v0.z; f[3] = v0.w;
        f[4] = v1.x; f[5] = v1.y; f[6] = v1.z; f[7] = v1.w;
    };
    auto storeA = [&](const float* f, int stg) {
        uint4 hi4;
        unsigned* hp = (unsigned*)&hi4;
#pragma unroll
        for (int j = 0; j < 4; j++)
            hp[j] = pack_h2(f[2 * j], f[2 * j + 1]);
        *(uint4*)(smem + stg * H_STG + (arow * HP + akc) * 2) = hi4;
    };
    auto loadB = [&](int k0, int stg) {
        size_t srcoff = (size_t)(bn + brow) * Kd + k0 + bseg * 8;
        cp16(smem + stg * H_STG + 5120 + (brow * HP + bseg * 8) * 2, h.bh + srcoff);
        cp_commit();
    };

    unsigned ah[2][4], bh2[2][2][4];
    auto ldfrag = [&](int ks, int buf, unsigned base) {
        int kb = ks * 16;
        ldsm4(ah[buf], base + (((wm * 16 + a_m) * HP) + kb + a_k) * 2);
#pragma unroll
        for (int np = 0; np < 2; np++)
            ldsm4(bh2[buf][np], base + 5120 + (((wn * 32 + np * 16 + b_n) * HP) + kb + b_k) * 2);
    };

    int nch = Kd / 32;
    float av[8];
    loadA(0, av);
    loadB(0, 0);
    for (int ch = 0; ch < nch; ch++) {
        int s = ch & 1;
        storeA(av, s);
        if (ch + 1 < nch) {
            loadB((ch + 1) * 32, s ^ 1);
            loadA((ch + 1) * 32, av);
            cp_wait<1>();
        } else {
            cp_wait<0>();
        }
        __syncthreads();
        unsigned base = sb + s * H_STG;
        ldfrag(0, 0, base);
#pragma unroll
        for (int ks = 0; ks < 2; ks++) {
            int cur = ks & 1;
            if (ks < 1) ldfrag(1, 1, base);
#pragma unroll
            for (int nt = 0; nt < 4; nt++)
                mma16816h(acc[nt], ah[cur], &bh2[cur][nt >> 1][(nt & 1) * 2]);
        }
        __syncthreads();
    }

    int lr = lane >> 2, lc = (lane & 3) << 1;
    if (h.transN) {
        float* smf = (float*)smem;
#pragma unroll
        for (int nt = 0; nt < 4; nt++) {
            int col = wn * 32 + nt * 8 + lc;
#pragma unroll
            for (int hh = 0; hh < 2; hh++) {
                int row = wm * 16 + lr + hh * 8;
                smf[row * 65 + col]     = acc[nt][hh * 2 + 0];
                smf[row * 65 + col + 1] = acc[nt][hh * 2 + 1];
            }
        }
        __syncthreads();
        int row = tid & 63, cgrp = tid >> 6;
        int grow = bm + row;
        int b = grow >> 12, n = grow & (N_ - 1);
#pragma unroll
        for (int cc = cgrp * 16; cc < cgrp * 16 + 16; cc++)
            h.out[((size_t)(b * C_ + bn + cc)) * N_ + n] = smf[row * 65 + cc];
        return;
    }
#pragma unroll
    for (int nt = 0; nt < 4; nt++) {
        int col = bn + wn * 32 + nt * 8 + lc;
#pragma unroll
        for (int hh = 0; hh < 2; hh++) {
            int row = bm + wm * 16 + lr + hh * 8;
            size_t o = (size_t)row * h.Nd + col;
            float v0 = acc[nt][hh * 2 + 0];
            float v1 = acc[nt][hh * 2 + 1];
            if (h.ep == 1) {
                v0 = 1.0f / (1.0f + __expf(-v0));
                v1 = 1.0f / (1.0f + __expf(-v1));
            } else if (h.ep == 2) {
                v0 = fmaxf(v0, 0.f); v0 = v0 * v0;
                v1 = fmaxf(v1, 0.f); v1 = v1 * v1;
            }
            if (h.Mul) { v0 *= h.Mul[o]; v1 *= h.Mul[o + 1]; }
            if (h.Res) { v0 += h.Res[o]; v1 += h.Res[o + 1]; }
            *(float2*)(h.out + o) = make_float2(v0, v1);
        }
    }
}

// ---------------- LayerNorm (optional 2-input sum + sum output) ----------------
__global__ void __launch_bounds__(128) k_ln(const float* __restrict__ X,
                                            const float* __restrict__ Xb,
                                            const float* __restrict__ g,
                                            const float* __restrict__ bb,
                                            float* __restrict__ Ysum,
                                            float* __restrict__ Y) {
    int m = blockIdx.x, c = threadIdx.x;
    size_t i = (size_t)m * C_ + c;
    float v = X[i];
    if (Xb) v += Xb[i];
    if (Ysum) Ysum[i] = v;
    float s = v, q = v * v;
#pragma unroll
    for (int off = 16; off >= 1; off >>= 1) {
        s += __shfl_xor_sync(0xffffffffu, s, off);
        q += __shfl_xor_sync(0xffffffffu, q, off);
    }
    __shared__ float s1[4], s2[4];
    int w = c >> 5;
    if ((c & 31) == 0) { s1[w] = s; s2[w] = q; }
    __syncthreads();
    s = s1[0] + s1[1] + s1[2] + s1[3];
    q = s2[0] + s2[1] + s2[2] + s2[3];
    float mu = s * (1.0f / C_);
    float var = q * (1.0f / C_) - mu * mu;
    Y[i] = (v - mu) * rsqrtf(var + 1e-5f) * g[c] + bb[c];
}

// ---------------- fused y-transpose (blocks 0..1023) + BN partials (1024..1279) ----------------
__global__ void __launch_bounds__(256) k_out_tb(const float* __restrict__ pts,
                                                float* __restrict__ out_y) {
    int tid = threadIdx.x;
    if (blockIdx.x < 1024) {
        __shared__ float t[32][33];
        int pb = blockIdx.x;
        int n0 = (pb & 127) * 32, c0 = ((pb >> 7) & 3) * 32, b = pb >> 9;
        int tx = tid & 31, ty = tid >> 5;
        for (int i = ty; i < 32; i += 8)
            t[i][tx] = pts[((size_t)(b * N_ + n0 + i)) * C_ + c0 + tx];
        __syncthreads();
        for (int i = ty; i < 32; i += 8)
            out_y[((size_t)(b * C_ + c0 + i)) * N_ + n0 + tx] = t[tx][i];
        return;
    }
    if (tid >= 128) return;
    int blk = blockIdx.x - 1024;
    int c = tid;
    float s = 0.f, q = 0.f;
    int base = blk * 32;
    for (int r = 0; r < 32; r++) {
        float v = pts[(size_t)(base + r) * C_ + c];
        s += v; q = fmaf(v, v, q);
    }
    g_p1[blk * C_ + c] = s;
    g_p2[blk * C_ + c] = q;
}

__global__ void __launch_bounds__(128) k_bnred(const float* __restrict__ bg,
                                               const float* __restrict__ bb) {
    int c = threadIdx.x;
    float s = 0.f, q = 0.f;
    for (int i = 0; i < 256; i++) { s += g_p1[i * C_ + c]; q += g_p2[i * C_ + c]; }
    float mu = s * (1.0f / M_);
    float var = q * (1.0f / M_) - mu * mu;
    float a = bg[c] * rsqrtf(var + 1e-5f);
    g_bnA[c] = a;
    g_bnB[c] = bb[c] - mu * a;
}

// ---------------- WKV ----------------
__global__ void __launch_bounds__(256) k_wkv(
    const float* __restrict__ kT, const float* __restrict__ vT,
    const float* __restrict__ sigr,
    const float* __restrict__ td, const float* __restrict__ tf,
    float* __restrict__ out)
{
    int warp = (blockIdx.x * 256 + threadIdx.x) >> 5;
    int lane = threadIdx.x & 31;
    int b = warp >> 7, c = warp & 127;
    float w = -expf(td[c]);
    float ew = expf(w);
    float etf = expf(tf[c]);
    int n0 = lane * 128;
    const float* kp = kT + ((size_t)(b * C_ + c)) * N_ + n0;
    const float* vp = vT + ((size_t)(b * C_ + c)) * N_ + n0;
    float A = 0.f, Bv = 0.f;
#pragma unroll 4
    for (int j = 0; j < 128; j++) {
        float ek = __expf(kp[j]);
        A = fmaf(A, ew, ek * vp[j]);
        Bv = fmaf(Bv, ew, ek);
    }
    float al = __expf(128.0f * w);
    float sA = A, sB = Bv, sal = al;
#pragma unroll
    for (int off = 1; off < 32; off <<= 1) {
        float pA = __shfl_up_sync(0xffffffffu, sA, off);
        float pB = __shfl_up_sync(0xffffffffu, sB, off);
        float pal = __shfl_up_sync(0xffffffffu, sal, off);
        if (lane >= off) {
            sA = fmaf(sal, pA, sA);
            sB = fmaf(sal, pB, sB);
            sal = sal * pal;
        }
    }
    float A0 = __shfl_up_sync(0xffffffffu, sA, 1);
    float B0 = __shfl_up_sync(0xffffffffu, sB, 1);
    if (lane == 0) { A0 = 0.f; B0 = 0.f; }
    A = A0; Bv = B0;
    const float* rp = sigr + ((size_t)(b * N_ + n0)) * C_ + c;
    float* op = out + ((size_t)(b * N_ + n0)) * C_ + c;
#pragma unroll 2
    for (int j = 0; j < 128; j++) {
        float kt = kp[j], vt = vp[j];
        float ek = __expf(kt);
        float ekf = etf * ek;
        float o = (A + ekf * vt) / (Bv + ekf);
        op[(size_t)j * C_] = o * rp[(size_t)j * C_];
        A = fmaf(A, ew, ek * vt);
        Bv = fmaf(Bv, ew, ek);
    }
}

// ---------------- head ----------------
__global__ void __launch_bounds__(256) k_head(const float* __restrict__ pts,
                                              const float* __restrict__ cw,
                                              const float* __restrict__ cb,
                                              float* __restrict__ label) {
    __shared__ float sw[CLS_ * C_];
    int tid = threadIdx.x;
    for (int i = tid; i < CLS_ * C_; i += 256) sw[i] = cw[i];
    __syncthreads();
    int m = blockIdx.x * 8 + (tid >> 5);
    int lane = tid & 31;
    float yn[4];
#pragma unroll
    for (int j = 0; j < 4; j++) {
        int c = lane + 32 * j;
        float v = fmaf(g_bnA[c], pts[(size_t)m * C_ + c], g_bnB[c]);
        yn[j] = fmaxf(v, 0.f);
    }
    int b = m >> 12, n = m & (N_ - 1);
#pragma unroll 1
    for (int d = 0; d < CLS_; d++) {
        float p = 0.f;
#pragma unroll
        for (int j = 0; j < 4; j++) p = fmaf(yn[j], sw[d * C_ + lane + 32 * j], p);
#pragma unroll
        for (int off = 16; off >= 1; off >>= 1) p += __shfl_xor_sync(0xffffffffu, p, off);
        if (lane == 0)
            label[((size_t)(b * CLS_ + d)) * N_ + n] = p + cb[d];
    }
}

// ---------------- host ----------------
extern "C" void kernel_launch(void* const* d_in, const int* in_sizes, int n_in,
                              void* d_out, int out_size) {
    const float* p        = (const float*)d_in[0];
    const float* x        = (const float*)d_in[1];
    const float* kp1_w    = (const float*)d_in[2];
    const float* kp2_w    = (const float*)d_in[3];
    const float* ln1_g    = (const float*)d_in[4];
    const float* ln1_b    = (const float*)d_in[5];
    const float* tdcy     = (const float*)d_in[6];
    const float* tfst     = (const float*)d_in[7];
    const float* mix_k    = (const float*)d_in[8];
    const float* mix_v    = (const float*)d_in[9];
    const float* mix_r    = (const float*)d_in[10];
    const float* att_wk   = (const float*)d_in[11];
    const float* att_wv   = (const float*)d_in[12];
    const float* att_wr   = (const float*)d_in[13];
    const float* att_wo   = (const float*)d_in[14];
    const float* ln2_g    = (const float*)d_in[15];
    const float* ln2_b    = (const float*)d_in[16];
    const float* cmix_k   = (const float*)d_in[17];
    const float* cmix_r   = (const float*)d_in[18];
    const float* ffn_wk   = (const float*)d_in[19];
    const float* ffn_wv   = (const float*)d_in[20];
    const float* ffn_wr   = (const float*)d_in[21];
    const float* bn_g     = (const float*)d_in[22];
    const float* bn_b     = (const float*)d_in[23];
    const float* conv_w   = (const float*)d_in[24];
    const float* conv_b   = (const float*)d_in[25];

    float* out_y = (float*)d_out;
    float* out_label = out_y + (size_t)B_ * C_ * N_;

    float *gf, *gx0, *gpts, *gxn, *grr, *gkT, *gvT, *gwkv, *gffn;
    cudaGetSymbolAddress((void**)&gf, g_f);
    cudaGetSymbolAddress((void**)&gx0, g_x0);
    cudaGetSymbolAddress((void**)&gpts, g_pts);
    cudaGetSymbolAddress((void**)&gxn, g_xn);
    cudaGetSymbolAddress((void**)&grr, g_rr);
    cudaGetSymbolAddress((void**)&gkT, g_kT);
    cudaGetSymbolAddress((void**)&gvT, g_vT);
    cudaGetSymbolAddress((void**)&gwkv, g_wkv);
    cudaGetSymbolAddress((void**)&gffn, g_ffn);

    __half *wak_h, *wav_h, *war_h, *wao_h, *wfk_h, *wfr_h, *wfv_h, *w1_h, *w2_h;
    cudaGetSymbolAddress((void**)&wak_h, g_wak_h);
    cudaGetSymbolAddress((void**)&wav_h, g_wav_h);
    cudaGetSymbolAddress((void**)&war_h, g_war_h);
    cudaGetSymbolAddress((void**)&wao_h, g_wao_h);
    cudaGetSymbolAddress((void**)&wfk_h, g_wfk_h);
    cudaGetSymbolAddress((void**)&wfr_h, g_wfr_h);
    cudaGetSymbolAddress((void**)&wfv_h, g_wfv_h);
    cudaGetSymbolAddress((void**)&w1_h, g_wT1_h);
    cudaGetSymbolAddress((void**)&w2_h, g_wT2_h);

    cudaFuncSetAttribute(k_mma_kpconv, cudaFuncAttributeMaxDynamicSharedMemorySize, SM_MMA);
    cudaFuncSetAttribute(k_hgemm3, cudaFuncAttributeMaxDynamicSharedMemorySize, H_SZ);

    // 1: geo setup  2: knn+prep  3: weight setup  4: build_fk (profiled)
    k_setup_geo<<<33, 256>>>(p);
    k_knn_prep<<<2048, 256>>>(x);
    k_setup_w<<<1584, 256>>>(kp1_w, kp2_w, att_wk, att_wv, att_wr, att_wo,
                             ffn_wk, ffn_wr, ffn_wv);
    k_build_fk<<<M_ / 2, 128>>>(gf);
    // KPConv 1 split-K: partials in gkT/gvT, combine -> gf (f1 = fk@w1 + f0)
    k_mma_kpconv<<<dim3(M_ / 64, 2), 256, SM_MMA>>>(w1_h, gf, nullptr, gkT, gvT);
    k_add2<<<1024, 256>>>((const float4*)gkT, (const float4*)gvT, (float4*)gf);
    // KPConv 2 split-K: pts = fk@w2 + f1 + x0 (combined inside LN below)
    k_build_fk<<<M_ / 2, 128>>>(gf);
    k_mma_kpconv<<<dim3(M_ / 64, 2), 256, SM_MMA>>>(w2_h, gf, gx0, gkT, gvT);

    // ---- RWKV spatial mix (LN fuses the split-K combine; writes gpts + gxn) ----
    k_ln<<<M_, 128>>>(gkT, gvT, ln1_g, ln1_b, gpts, gxn);
    {
        HA3 qkv;
        qkv.a[0] = { wak_h, gkT, mix_k, nullptr, nullptr, 0, 1, C_ };
        qkv.a[1] = { wav_h, gvT, mix_v, nullptr, nullptr, 0, 1, C_ };
        qkv.a[2] = { war_h, grr, mix_r, nullptr, nullptr, 1, 0, C_ };
        k_hgemm3<<<dim3(128, 2, 3), 256, H_SZ>>>(gxn, qkv, C_);
    }
    k_wkv<<<32, 256>>>(gkT, gvT, grr, tdcy, tfst, gwkv);
    {
        HA3 wo;
        wo.a[0] = { wao_h, gpts, nullptr, gpts, nullptr, 0, 0, C_ };
        wo.a[1] = wo.a[0]; wo.a[2] = wo.a[0];
        k_hgemm3<<<dim3(128, 2, 1), 256, H_SZ>>>(gwkv, wo, C_);
    }

    // ---- channel mix ----
    k_ln<<<M_, 128>>>(gpts, nullptr, ln2_g, ln2_b, nullptr, gxn);
    {
        HA3 fkr;
        fkr.a[0] = { wfk_h, gffn, cmix_k, nullptr, nullptr, 2, 0, F_ };
        fkr.a[1] = { wfr_h, grr,  cmix_r, nullptr, nullptr, 1, 0, C_ };
        fkr.a[2] = fkr.a[0];
        k_hgemm3<<<dim3(128, 8, 2), 256, H_SZ>>>(gxn, fkr, C_);
    }
    {
        HA3 fv;
        fv.a[0] = { wfv_h, gpts, nullptr, gpts, grr, 0, 0, C_ };
        fv.a[1] = fv.a[0]; fv.a[2] = fv.a[0];
        k_hgemm3<<<dim3(128, 2, 1), 256, H_SZ>>>(gffn, fv, F_);
    }

    // ---- outputs (transpose + BN partials fused) ----
    k_out_tb<<<1280, 256>>>(gpts, out_y);
    k_bnred<<<1, 128>>>(bn_g, bn_b);
    k_head<<<M_ / 8, 256>>>(gpts, conv_w, conv_b, out_label);
    (void)in_sizes; (void)n_in; (void)out_size;
}

// round 16
// speedup vs baseline: 1.0313x; 1.0313x over previous
#include <cuda_runtime.h>
#include <cuda_bf16.h>
#include <cuda_fp16.h>
#include <math.h>

static constexpr int B_ = 2, N_ = 4096, C_ = 128, K_ = 16, P_ = 43, CLS_ = 16, F_ = 512;
static constexpr int M_ = B_ * N_;
static constexpr int PC_ = P_ * C_;          // 5504
static constexpr float R2_ = 0.01f;          // RADIUS^2
static constexpr float INV_SIG_ = 10.0f;     // 1/RADIUS

// ---------------- static device scratch ----------------
__device__ float4 g_xyzw[M_];
__device__ int    g_nbr[M_ * K_];
__device__ float  g_kpts[P_ * 3];
__device__ float  g_f[M_ * C_];
__device__ float  g_x0[M_ * C_];
__device__ __half g_fk_h[(size_t)M_ * PC_];                 // 90 MB, single fp16
__device__ __half g_wT1_h[(size_t)C_ * PC_];
__device__ __half g_wT2_h[(size_t)C_ * PC_];
__device__ __half g_wak_h[C_ * C_];
__device__ __half g_wav_h[C_ * C_];
__device__ __half g_war_h[C_ * C_];
__device__ __half g_wao_h[C_ * C_];
__device__ __half g_wfk_h[F_ * C_];
__device__ __half g_wfr_h[C_ * C_];
__device__ __half g_wfv_h[C_ * F_];
__device__ float g_pts[M_ * C_];
__device__ float g_xn[M_ * C_];
__device__ float g_rr[M_ * C_];
__device__ float g_kT[M_ * C_];
__device__ float g_vT[M_ * C_];
__device__ float g_wkv[M_ * C_];
__device__ float g_ffn[M_ * F_];
__device__ float g_p1[256 * C_];
__device__ float g_p2[256 * C_];
__device__ float g_bnA[C_];
__device__ float g_bnB[C_];

// ---------------- helpers ----------------
__device__ __forceinline__ unsigned smem_u32(const void* p) {
    unsigned a;
    asm("{ .reg .u64 t; cvta.to.shared.u64 t, %1; cvt.u32.u64 %0, t; }" : "=r"(a) : "l"(p));
    return a;
}
__device__ __forceinline__ void cp16(void* dst, const void* src) {
    unsigned d;
    asm("{ .reg .u64 t; cvta.to.shared.u64 t, %1; cvt.u32.u64 %0, t; }" : "=r"(d) : "l"(dst));
    asm volatile("cp.async.cg.shared.global [%0], [%1], 16;" :: "r"(d), "l"(src));
}
__device__ __forceinline__ void cp_commit() {
    asm volatile("cp.async.commit_group;" ::: "memory");
}
template <int N>
__device__ __forceinline__ void cp_wait() {
    asm volatile("cp.async.wait_group %0;" :: "n"(N) : "memory");
}
__device__ __forceinline__ void mma16816h(float* c, const unsigned* a, const unsigned* b) {
    asm volatile(
        "mma.sync.aligned.m16n8k16.row.col.f32.f16.f16.f32 "
        "{%0,%1,%2,%3}, {%4,%5,%6,%7}, {%8,%9}, {%0,%1,%2,%3};"
        : "+f"(c[0]), "+f"(c[1]), "+f"(c[2]), "+f"(c[3])
        : "r"(a[0]), "r"(a[1]), "r"(a[2]), "r"(a[3]), "r"(b[0]), "r"(b[1]));
}
__device__ __forceinline__ void ldsm4(unsigned* r, unsigned a) {
    asm volatile("ldmatrix.sync.aligned.m8n8.x4.shared.b16 {%0,%1,%2,%3}, [%4];"
        : "=r"(r[0]), "=r"(r[1]), "=r"(r[2]), "=r"(r[3]) : "r"(a));
}
__device__ __forceinline__ unsigned pack_h2(float a, float b) {
    __half2 h;
    h.x = __float2half(a); h.y = __float2half(b);
    return *reinterpret_cast<unsigned*>(&h);
}

// ---------------- setup part 1: kpts + xyz ----------------
__global__ void __launch_bounds__(256) k_setup_geo(const float* __restrict__ p) {
    int bid = blockIdx.x;
    int tid = threadIdx.x;
    if (bid == 0) {
        int t = tid;
        if (t < P_) {
            double x = 0.0, y = 0.0, z = 0.0;
            if (t > 0) {
                int mc = (t <= 14) ? 14 : 28;
                double scale = (t <= 14) ? 0.05 : 0.1;
                int i0 = (t <= 14) ? (t - 1) : (t - 15);
                double i = i0 + 0.5;
                double phi = acos(1.0 - 2.0 * i / (double)mc);
                double theta = 3.141592653589793 * (1.0 + sqrt(5.0)) * i;
                x = cos(theta) * sin(phi) * scale;
                y = sin(theta) * sin(phi) * scale;
                z = cos(phi) * scale;
            }
            g_kpts[t * 3 + 0] = (float)x;
            g_kpts[t * 3 + 1] = (float)y;
            g_kpts[t * 3 + 2] = (float)z;
        }
    } else {
        int m = (bid - 1) * 256 + tid;
        int b = m / N_, n = m - b * N_;
        float x = p[((size_t)b * 3 + 0) * N_ + n];
        float y = p[((size_t)b * 3 + 1) * N_ + n];
        float z = p[((size_t)b * 3 + 2) * N_ + n];
        g_xyzw[m] = make_float4(x, y, z, fmaf(x, x, fmaf(y, y, z * z)));
    }
}

// ---------------- setup part 2: all weight transposes (fp16) ----------------
__global__ void __launch_bounds__(256) k_setup_w(
    const float* __restrict__ kp1, const float* __restrict__ kp2,
    const float* __restrict__ awk, const float* __restrict__ awv,
    const float* __restrict__ awr, const float* __restrict__ awo,
    const float* __restrict__ fwk, const float* __restrict__ fwr,
    const float* __restrict__ fwv)
{
    int bid = blockIdx.x;
    int tid = threadIdx.x;
    const float* src; __half* hi; int Kd, Nd, lt;
    if (bid < 688)       { src = kp1; hi = g_wT1_h; Kd = PC_; Nd = C_; lt = bid; }
    else if (bid < 1376) { src = kp2; hi = g_wT2_h; Kd = PC_; Nd = C_; lt = bid - 688; }
    else if (bid < 1392) { src = awk; hi = g_wak_h; Kd = C_; Nd = C_; lt = bid - 1376; }
    else if (bid < 1408) { src = awv; hi = g_wav_h; Kd = C_; Nd = C_; lt = bid - 1392; }
    else if (bid < 1424) { src = awr; hi = g_war_h; Kd = C_; Nd = C_; lt = bid - 1408; }
    else if (bid < 1440) { src = awo; hi = g_wao_h; Kd = C_; Nd = C_; lt = bid - 1424; }
    else if (bid < 1504) { src = fwk; hi = g_wfk_h; Kd = C_; Nd = F_; lt = bid - 1440; }
    else if (bid < 1520) { src = fwr; hi = g_wfr_h; Kd = C_; Nd = C_; lt = bid - 1504; }
    else                 { src = fwv; hi = g_wfv_h; Kd = F_; Nd = C_; lt = bid - 1520; }
    int tn = Nd / 32;
    int kt = lt / tn, nt = lt - kt * tn;
    int k0 = kt * 32, n0 = nt * 32;
    __shared__ float sm[32][33];
    int tx = tid & 31, ty = tid >> 5;
    for (int i = ty; i < 32; i += 8)
        sm[i][tx] = src[(size_t)(k0 + i) * Nd + n0 + tx];
    __syncthreads();
    for (int i = ty; i < 32; i += 8)
        hi[(size_t)(n0 + i) * Kd + k0 + tx] = __float2half(sm[tx][i]);
}

// ---------------- knn (blocks 0..1023) + feature transpose (1024..2047) ----------------
__global__ void __launch_bounds__(256) k_knn_prep(const float* __restrict__ x) {
    __shared__ float4 tile[1024];
    int tid = threadIdx.x;
    if (blockIdx.x >= 1024) {
        float (*sm)[33] = reinterpret_cast<float(*)[33]>(tile);
        int pb = blockIdx.x - 1024;
        int c0 = (pb & 3) * 32, n0 = ((pb >> 2) & 127) * 32, b = pb >> 9;
        int tx = tid & 31, ty = tid >> 5;
        for (int i = ty; i < 32; i += 8)
            sm[i][tx] = x[((size_t)(b * C_ + c0 + i)) * N_ + n0 + tx];
        __syncthreads();
        for (int i = ty; i < 32; i += 8) {
            float v = sm[tx][i];
            size_t o = ((size_t)(b * N_ + n0 + i)) * C_ + c0 + tx;
            g_f[o] = v;
            g_x0[o] = v;
        }
        return;
    }
    int wid = tid >> 5, lane = tid & 31;
    int m = blockIdx.x * 8 + wid;
    int base = (m >> 12) * N_;
    float4 q = g_xyzw[m];
    float bd[K_]; int bi[K_];
#pragma unroll
    for (int k = 0; k < K_; k++) { bd[k] = 3.4e38f; bi[k] = 0x7FFFFFFF; }
    for (int t0 = 0; t0 < N_; t0 += 1024) {
        __syncthreads();
        for (int j = tid; j < 1024; j += 256) tile[j] = g_xyzw[base + t0 + j];
        __syncthreads();
#pragma unroll 2
        for (int t = 0; t < 32; t++) {
            int j = t * 32 + lane;
            float4 c = tile[j];
            float dot = fmaf(q.x, c.x, fmaf(q.y, c.y, q.z * c.z));
            float d2 = q.w + c.w - 2.0f * dot;
            if (d2 <= R2_ && d2 < bd[K_ - 1]) {
                int idx = t0 + j;
#pragma unroll
                for (int k = K_ - 1; k >= 0; k--) {
                    float pd = (k > 0) ? bd[k - 1] : -1.0f;
                    if (pd > d2) {
                        if (k > 0) { bd[k] = bd[k - 1]; bi[k] = bi[k - 1]; }
                    } else if (bd[k] > d2) {
                        bd[k] = d2; bi[k] = idx;
                    }
                }
            }
        }
    }
    float outd = 3.4e38f; int outi = 0x7FFFFFFF;
    for (int r = 0; r < K_; r++) {
        unsigned fb = __float_as_uint(bd[0]);
        fb = (fb & 0x80000000u) ? ~fb : (fb | 0x80000000u);
        unsigned long long key = (((unsigned long long)fb) << 32) | (unsigned)bi[0];
        unsigned long long kmin = key;
#pragma unroll
        for (int off = 16; off >= 1; off >>= 1) {
            unsigned long long o = __shfl_xor_sync(0xffffffffu, kmin, off);
            if (o < kmin) kmin = o;
        }
        if (key == kmin) {
#pragma unroll
            for (int k = 0; k < K_ - 1; k++) { bd[k] = bd[k + 1]; bi[k] = bi[k + 1]; }
            bd[K_ - 1] = 3.4e38f; bi[K_ - 1] = 0x7FFFFFFF;
        }
        if (lane == r) {
            unsigned tu = (unsigned)(kmin >> 32);
            unsigned ob = (tu & 0x80000000u) ? (tu ^ 0x80000000u) : ~tu;
            outd = __uint_as_float(ob);
            outi = (int)(unsigned)(kmin & 0xffffffffu);
        }
    }
    int wi0 = __shfl_sync(0xffffffffu, outi, 0);
    if (lane < K_) {
        int sel = (outd <= R2_) ? outi : wi0;
        g_nbr[m * K_ + lane] = base + sel;
    }
}

// ---------------- build fk (single fp16) — R14 version (measured 48.4us) ----------------
__global__ void __launch_bounds__(128) k_build_fk(const float* __restrict__ fin) {
    int m0 = blockIdx.x * 2;
    int tid = threadIdx.x;
    int sub = tid >> 6, t = tid & 63, c0 = t * 2;
    __shared__ float infl[2][P_][20];
    __shared__ float nx[2][K_], ny[2][K_], nz[2][K_];
    __shared__ int nidx[2][K_];
    if (tid < 2 * K_) {
        int ss = tid >> 4, kk = tid & 15;
        int nb = g_nbr[(m0 + ss) * K_ + kk];
        nidx[ss][kk] = nb;
        float4 nq = g_xyzw[nb];
        nx[ss][kk] = nq.x; ny[ss][kk] = nq.y; nz[ss][kk] = nq.z;
    }
    __syncthreads();
    for (int e = tid; e < 2 * P_ * K_; e += 128) {
        int ss = e / (P_ * K_);
        int rem = e - ss * P_ * K_;
        int pp = rem >> 4, k = rem & 15;
        float4 cq = g_xyzw[m0 + ss];
        float rx = nx[ss][k] - cq.x, ry = ny[ss][k] - cq.y, rz = nz[ss][k] - cq.z;
        float dx = rx - g_kpts[pp * 3], dy = ry - g_kpts[pp * 3 + 1], dz = rz - g_kpts[pp * 3 + 2];
        float d = sqrtf(fmaf(dx, dx, fmaf(dy, dy, dz * dz)) + 1e-12f);
        infl[ss][pp][k] = fmaxf(0.0f, 1.0f - d * INV_SIG_);
    }
    __syncthreads();
    float2 Fv[K_];
#pragma unroll
    for (int k = 0; k < K_; k++)
        Fv[k] = *(const float2*)(fin + (size_t)nidx[sub][k] * C_ + c0);
    size_t dstb = (size_t)(m0 + sub) * PC_ + c0;
#pragma unroll 1
    for (int pp = 0; pp < P_; pp++) {
        float a0 = 0.f, a1 = 0.f;
#pragma unroll
        for (int k4 = 0; k4 < 4; k4++) {
            float4 w = *(const float4*)&infl[sub][pp][k4 * 4];
            a0 = fmaf(w.x, Fv[k4 * 4 + 0].x, a0); a1 = fmaf(w.x, Fv[k4 * 4 + 0].y, a1);
            a0 = fmaf(w.y, Fv[k4 * 4 + 1].x, a0); a1 = fmaf(w.y, Fv[k4 * 4 + 1].y, a1);
            a0 = fmaf(w.z, Fv[k4 * 4 + 2].x, a0); a1 = fmaf(w.z, Fv[k4 * 4 + 2].y, a1);
            a0 = fmaf(w.w, Fv[k4 * 4 + 3].x, a0); a1 = fmaf(w.w, Fv[k4 * 4 + 3].y, a1);
        }
        *reinterpret_cast<unsigned*>(g_fk_h + dstb + (size_t)pp * C_) = pack_h2(a0, a1);
    }
}

// ---------------- HMMA KPConv GEMM: split-K=2, fragment-pipelined, fp16 ----------------
static constexpr int GBK = 64;
static constexpr int HCH_ = (PC_ / GBK) / 2;             // 43 chunks per half
static constexpr int AP = 72;
static constexpr int ST_B  = 64 * AP * 2;                // 9216
static constexpr int ST_SZ = ST_B + 128 * AP * 2;        // 27648
static constexpr int SM_MMA = 3 * ST_SZ;                 // 82944

__global__ void __launch_bounds__(256) k_mma_kpconv(
    const __half* __restrict__ Bh,
    const float* __restrict__ Res, const float* __restrict__ Res2,
    float* __restrict__ Out0, float* __restrict__ Out1)
{
    extern __shared__ char smem[];
    unsigned sb = smem_u32(smem);
    int tid = threadIdx.x;
    int bm = blockIdx.x * 64;
    int half = blockIdx.y;
    int kbase = half * HCH_;
    int wid = tid >> 5, lane = tid & 31;
    int wm = wid & 1, wn = wid >> 1;
    int li = lane & 7, lm2 = lane >> 3;
    int a_m = (lm2 & 1) * 8 + li, a_k = (lm2 >> 1) * 8;
    int b_n = (lm2 >> 1) * 8 + li, b_k = (lm2 & 1) * 8;

    float acc[2][4][4];
#pragma unroll
    for (int i = 0; i < 2; i++)
#pragma unroll
        for (int j = 0; j < 4; j++)
#pragma unroll
            for (int q = 0; q < 4; q++) acc[i][j][q] = 0.f;

    auto load_chunk = [&](int ch, int s) {
        int k0 = ch * GBK;
        char* st = smem + s * ST_SZ;
#pragma unroll
        for (int i = 0; i < 2; i++) {
            int idx = tid + i * 256;
            int row = idx >> 3, seg = idx & 7;
            size_t srcoff = (size_t)(bm + row) * PC_ + k0 + seg * 8;
            cp16(st + (row * AP + seg * 8) * 2, g_fk_h + srcoff);
        }
#pragma unroll
        for (int i = 0; i < 4; i++) {
            int idx = tid + i * 256;
            int row = idx >> 3, seg = idx & 7;
            size_t srcoff = (size_t)row * PC_ + k0 + seg * 8;
            cp16(st + ST_B + (row * AP + seg * 8) * 2, Bh + srcoff);
        }
        cp_commit();
    };

    unsigned ah[2][2][4], bh[2][2][4];
    auto ldfrag = [&](int ks, int buf, unsigned stb) {
        int kb = ks * 16;
#pragma unroll
        for (int mt = 0; mt < 2; mt++)
            ldsm4(ah[buf][mt], stb + (((wm * 32 + mt * 16 + a_m) * AP) + kb + a_k) * 2);
#pragma unroll
        for (int np = 0; np < 2; np++)
            ldsm4(bh[buf][np], stb + ST_B + (((wn * 32 + np * 16 + b_n) * AP) + kb + b_k) * 2);
    };

    load_chunk(kbase + 0, 0);
    load_chunk(kbase + 1, 1);
    for (int ch = 0; ch < HCH_; ch++) {
        int s = ch % 3;
        if (ch + 2 < HCH_) { load_chunk(kbase + ch + 2, (ch + 2) % 3); cp_wait<2>(); }
        else if (ch + 1 < HCH_) cp_wait<1>();
        else cp_wait<0>();
        __syncthreads();
        unsigned stb = sb + s * ST_SZ;
        ldfrag(0, 0, stb);
#pragma unroll
        for (int ks = 0; ks < 4; ks++) {
            int cur = ks & 1;
            if (ks < 3) ldfrag(ks + 1, cur ^ 1, stb);
#pragma unroll
            for (int mt = 0; mt < 2; mt++)
#pragma unroll
                for (int nt = 0; nt < 4; nt++)
                    mma16816h(acc[mt][nt], ah[cur][mt], &bh[cur][nt >> 1][(nt & 1) * 2]);
        }
        __syncthreads();
    }

    int lr = lane >> 2;
    float* Out = half ? Out1 : Out0;
#pragma unroll
    for (int mt = 0; mt < 2; mt++) {
#pragma unroll
        for (int nt = 0; nt < 4; nt++) {
            int col = wn * 32 + nt * 8 + ((lane & 3) << 1);
#pragma unroll
            for (int h = 0; h < 2; h++) {
                int row = bm + wm * 32 + mt * 16 + lr + h * 8;
                size_t o = (size_t)row * C_ + col;
                float v0 = acc[mt][nt][h * 2 + 0];
                float v1 = acc[mt][nt][h * 2 + 1];
                if (half == 0) {
                    v0 += Res[o]; v1 += Res[o + 1];
                    if (Res2) { v0 += Res2[o]; v1 += Res2[o + 1]; }
                }
                *(float2*)(Out + o) = make_float2(v0, v1);
            }
        }
    }
}

// ---------------- combine split-K partials ----------------
__global__ void __launch_bounds__(256) k_add2(const float4* __restrict__ a,
                                              const float4* __restrict__ b,
                                              float4* __restrict__ o) {
    int i = blockIdx.x * 256 + threadIdx.x;
    float4 x = a[i], y = b[i];
    o[i] = make_float4(x.x + y.x, x.y + y.y, x.z + y.z, x.w + y.w);
}

// ---------------- batched HMMA small GEMM (single fp16, pipelined) ----------------
struct HA {
    const __half* bh;
    float* out; const float* mix; const float* Res; const float* Mul;
    int ep; int transN; int Nd;
};
struct HA3 { HA a[3]; };

static constexpr int HP = 40;
static constexpr int H_STG = 10240;
static constexpr int H_SZ = 2 * H_STG;

__global__ void __launch_bounds__(256) k_hgemm3(const float* __restrict__ A, HA3 args, int Kd) {
    HA h = args.a[blockIdx.z];
    int bn = blockIdx.y * 64;
    if (bn >= h.Nd) return;
    extern __shared__ char smem[];
    unsigned sb = smem_u32(smem);
    int tid = threadIdx.x;
    int bm = blockIdx.x * 64;
    int wid = tid >> 5, lane = tid & 31;
    int wm = wid & 3, wn = wid >> 2;
    int li = lane & 7, lm2 = lane >> 3;
    int a_m = (lm2 & 1) * 8 + li, a_k = (lm2 >> 1) * 8;
    int b_n = (lm2 >> 1) * 8 + li, b_k = (lm2 & 1) * 8;

    int arow = tid >> 2, akc = (tid & 3) * 8;
    int an = (bm + arow) & (N_ - 1);
    int brow = tid >> 2, bseg = tid & 3;

    float acc[4][4];
#pragma unroll
    for (int j = 0; j < 4; j++)
#pragma unroll
        for (int q = 0; q < 4; q++) acc[j][q] = 0.f;

    auto loadA = [&](int k0, float* f) {
        const float* ap = A + (size_t)(bm + arow) * Kd + k0 + akc;
        float4 v0 = *(const float4*)ap;
        float4 v1 = *(const float4*)(ap + 4);
        if (h.mix) {
            float4 p0 = make_float4(0.f, 0.f, 0.f, 0.f), p1 = p0;
            if (an != 0) {
                p0 = *(const float4*)(ap - Kd);
                p1 = *(const float4*)(ap - Kd + 4);
            }
            float4 m0 = *(const float4*)(h.mix + k0 + akc);
            float4 m1 = *(const float4*)(h.mix + k0 + akc + 4);
            v0.x = m0.x * v0.x + (1.f - m0.x) * p0.x;
            v0.y = m0.y * v0.y + (1.f - m0.y) * p0.y;
            v0.z = m0.z * v0.z + (1.f - m0.z) * p0.z;
            v0.w = m0.w * v0.w + (1.f - m0.w) * p0.w;
            v1.x = m1.x * v1.x + (1.f - m1.x) * p1.x;
            v1.y = m1.y * v1.y + (1.f - m1.y) * p1.y;
            v1.z = m1.z * v1.z + (1.f - m1.z) * p1.z;
            v1.w = m1.w * v1.w + (1.f - m1.w) * p1.w;
        }
        f[0] = v0.x; f[1] = v0.y; f[2] = v0.z; f[3] = v0.w;
        f[4] = v1.x; f[5] = v1.y; f[6] = v1.z; f[7] = v1.w;
    };
    auto storeA = [&](const float* f, int stg) {
        uint4 hi4;
        unsigned* hp = (unsigned*)&hi4;
#pragma unroll
        for (int j = 0; j < 4; j++)
            hp[j] = pack_h2(f[2 * j], f[2 * j + 1]);
        *(uint4*)(smem + stg * H_STG + (arow * HP + akc) * 2) = hi4;
    };
    auto loadB = [&](int k0, int stg) {
        size_t srcoff = (size_t)(bn + brow) * Kd + k0 + bseg * 8;
        cp16(smem + stg * H_STG + 5120 + (brow * HP + bseg * 8) * 2, h.bh + srcoff);
        cp_commit();
    };

    unsigned ah[2][4], bh2[2][2][4];
    auto ldfrag = [&](int ks, int buf, unsigned base) {
        int kb = ks * 16;
        ldsm4(ah[buf], base + (((wm * 16 + a_m) * HP) + kb + a_k) * 2);
#pragma unroll
        for (int np = 0; np < 2; np++)
            ldsm4(bh2[buf][np], base + 5120 + (((wn * 32 + np * 16 + b_n) * HP) + kb + b_k) * 2);
    };

    int nch = Kd / 32;
    float av[8];
    loadA(0, av);
    loadB(0, 0);
    for (int ch = 0; ch < nch; ch++) {
        int s = ch & 1;
        storeA(av, s);
        if (ch + 1 < nch) {
            loadB((ch + 1) * 32, s ^ 1);
            loadA((ch + 1) * 32, av);
            cp_wait<1>();
        } else {
            cp_wait<0>();
        }
        __syncthreads();
        unsigned base = sb + s * H_STG;
        ldfrag(0, 0, base);
#pragma unroll
        for (int ks = 0; ks < 2; ks++) {
            int cur = ks & 1;
            if (ks < 1) ldfrag(1, 1, base);
#pragma unroll
            for (int nt = 0; nt < 4; nt++)
                mma16816h(acc[nt], ah[cur], &bh2[cur][nt >> 1][(nt & 1) * 2]);
        }
        __syncthreads();
    }

    int lr = lane >> 2, lc = (lane & 3) << 1;
    if (h.transN) {
        float* smf = (float*)smem;
#pragma unroll
        for (int nt = 0; nt < 4; nt++) {
            int col = wn * 32 + nt * 8 + lc;
#pragma unroll
            for (int hh = 0; hh < 2; hh++) {
                int row = wm * 16 + lr + hh * 8;
                smf[row * 65 + col]     = acc[nt][hh * 2 + 0];
                smf[row * 65 + col + 1] = acc[nt][hh * 2 + 1];
            }
        }
        __syncthreads();
        int row = tid & 63, cgrp = tid >> 6;
        int grow = bm + row;
        int b = grow >> 12, n = grow & (N_ - 1);
#pragma unroll
        for (int cc = cgrp * 16; cc < cgrp * 16 + 16; cc++)
            h.out[((size_t)(b * C_ + bn + cc)) * N_ + n] = smf[row * 65 + cc];
        return;
    }
#pragma unroll
    for (int nt = 0; nt < 4; nt++) {
        int col = bn + wn * 32 + nt * 8 + lc;
#pragma unroll
        for (int hh = 0; hh < 2; hh++) {
            int row = bm + wm * 16 + lr + hh * 8;
            size_t o = (size_t)row * h.Nd + col;
            float v0 = acc[nt][hh * 2 + 0];
            float v1 = acc[nt][hh * 2 + 1];
            if (h.ep == 1) {
                v0 = 1.0f / (1.0f + __expf(-v0));
                v1 = 1.0f / (1.0f + __expf(-v1));
            } else if (h.ep == 2) {
                v0 = fmaxf(v0, 0.f); v0 = v0 * v0;
                v1 = fmaxf(v1, 0.f); v1 = v1 * v1;
            }
            if (h.Mul) { v0 *= h.Mul[o]; v1 *= h.Mul[o + 1]; }
            if (h.Res) { v0 += h.Res[o]; v1 += h.Res[o + 1]; }
            *(float2*)(h.out + o) = make_float2(v0, v1);
        }
    }
}

// ---------------- LayerNorm (optional 2-input sum + sum output) ----------------
__global__ void __launch_bounds__(128) k_ln(const float* __restrict__ X,
                                            const float* __restrict__ Xb,
                                            const float* __restrict__ g,
                                            const float* __restrict__ bb,
                                            float* __restrict__ Ysum,
                                            float* __restrict__ Y) {
    int m = blockIdx.x, c = threadIdx.x;
    size_t i = (size_t)m * C_ + c;
    float v = X[i];
    if (Xb) v += Xb[i];
    if (Ysum) Ysum[i] = v;
    float s = v, q = v * v;
#pragma unroll
    for (int off = 16; off >= 1; off >>= 1) {
        s += __shfl_xor_sync(0xffffffffu, s, off);
        q += __shfl_xor_sync(0xffffffffu, q, off);
    }
    __shared__ float s1[4], s2[4];
    int w = c >> 5;
    if ((c & 31) == 0) { s1[w] = s; s2[w] = q; }
    __syncthreads();
    s = s1[0] + s1[1] + s1[2] + s1[3];
    q = s2[0] + s2[1] + s2[2] + s2[3];
    float mu = s * (1.0f / C_);
    float var = q * (1.0f / C_) - mu * mu;
    Y[i] = (v - mu) * rsqrtf(var + 1e-5f) * g[c] + bb[c];
}

// ---------------- fused y-transpose (blocks 0..1023) + BN partials (1024..1279) ----------------
__global__ void __launch_bounds__(256) k_out_tb(const float* __restrict__ pts,
                                                float* __restrict__ out_y) {
    int tid = threadIdx.x;
    if (blockIdx.x < 1024) {
        __shared__ float t[32][33];
        int pb = blockIdx.x;
        int n0 = (pb & 127) * 32, c0 = ((pb >> 7) & 3) * 32, b = pb >> 9;
        int tx = tid & 31, ty = tid >> 5;
        for (int i = ty; i < 32; i += 8)
            t[i][tx] = pts[((size_t)(b * N_ + n0 + i)) * C_ + c0 + tx];
        __syncthreads();
        for (int i = ty; i < 32; i += 8)
            out_y[((size_t)(b * C_ + c0 + i)) * N_ + n0 + tx] = t[tx][i];
        return;
    }
    if (tid >= 128) return;
    int blk = blockIdx.x - 1024;
    int c = tid;
    float s = 0.f, q = 0.f;
    int base = blk * 32;
    for (int r = 0; r < 32; r++) {
        float v = pts[(size_t)(base + r) * C_ + c];
        s += v; q = fmaf(v, v, q);
    }
    g_p1[blk * C_ + c] = s;
    g_p2[blk * C_ + c] = q;
}

__global__ void __launch_bounds__(128) k_bnred(const float* __restrict__ bg,
                                               const float* __restrict__ bb) {
    int c = threadIdx.x;
    float s = 0.f, q = 0.f;
    for (int i = 0; i < 256; i++) { s += g_p1[i * C_ + c]; q += g_p2[i * C_ + c]; }
    float mu = s * (1.0f / M_);
    float var = q * (1.0f / M_) - mu * mu;
    float a = bg[c] * rsqrtf(var + 1e-5f);
    g_bnA[c] = a;
    g_bnB[c] = bb[c] - mu * a;
}

// ---------------- WKV ----------------
__global__ void __launch_bounds__(256) k_wkv(
    const float* __restrict__ kT, const float* __restrict__ vT,
    const float* __restrict__ sigr,
    const float* __restrict__ td, const float* __restrict__ tf,
    float* __restrict__ out)
{
    int warp = (blockIdx.x * 256 + threadIdx.x) >> 5;
    int lane = threadIdx.x & 31;
    int b = warp >> 7, c = warp & 127;
    float w = -expf(td[c]);
    float ew = expf(w);
    float etf = expf(tf[c]);
    int n0 = lane * 128;
    const float* kp = kT + ((size_t)(b * C_ + c)) * N_ + n0;
    const float* vp = vT + ((size_t)(b * C_ + c)) * N_ + n0;
    float A = 0.f, Bv = 0.f;
#pragma unroll 4
    for (int j = 0; j < 128; j++) {
        float ek = __expf(kp[j]);
        A = fmaf(A, ew, ek * vp[j]);
        Bv = fmaf(Bv, ew, ek);
    }
    float al = __expf(128.0f * w);
    float sA = A, sB = Bv, sal = al;
#pragma unroll
    for (int off = 1; off < 32; off <<= 1) {
        float pA = __shfl_up_sync(0xffffffffu, sA, off);
        float pB = __shfl_up_sync(0xffffffffu, sB, off);
        float pal = __shfl_up_sync(0xffffffffu, sal, off);
        if (lane >= off) {
            sA = fmaf(sal, pA, sA);
            sB = fmaf(sal, pB, sB);
            sal = sal * pal;
        }
    }
    float A0 = __shfl_up_sync(0xffffffffu, sA, 1);
    float B0 = __shfl_up_sync(0xffffffffu, sB, 1);
    if (lane == 0) { A0 = 0.f; B0 = 0.f; }
    A = A0; Bv = B0;
    const float* rp = sigr + ((size_t)(b * N_ + n0)) * C_ + c;
    float* op = out + ((size_t)(b * N_ + n0)) * C_ + c;
#pragma unroll 2
    for (int j = 0; j < 128; j++) {
        float kt = kp[j], vt = vp[j];
        float ek = __expf(kt);
        float ekf = etf * ek;
        float o = (A + ekf * vt) / (Bv + ekf);
        op[(size_t)j * C_] = o * rp[(size_t)j * C_];
        A = fmaf(A, ew, ek * vt);
        Bv = fmaf(Bv, ew, ek);
    }
}

// ---------------- head ----------------
__global__ void __launch_bounds__(256) k_head(const float* __restrict__ pts,
                                              const float* __restrict__ cw,
                                              const float* __restrict__ cb,
                                              float* __restrict__ label) {
    __shared__ float sw[CLS_ * C_];
    int tid = threadIdx.x;
    for (int i = tid; i < CLS_ * C_; i += 256) sw[i] = cw[i];
    __syncthreads();
    int m = blockIdx.x * 8 + (tid >> 5);
    int lane = tid & 31;
    float yn[4];
#pragma unroll
    for (int j = 0; j < 4; j++) {
        int c = lane + 32 * j;
        float v = fmaf(g_bnA[c], pts[(size_t)m * C_ + c], g_bnB[c]);
        yn[j] = fmaxf(v, 0.f);
    }
    int b = m >> 12, n = m & (N_ - 1);
#pragma unroll 1
    for (int d = 0; d < CLS_; d++) {
        float p = 0.f;
#pragma unroll
        for (int j = 0; j < 4; j++) p = fmaf(yn[j], sw[d * C_ + lane + 32 * j], p);
#pragma unroll
        for (int off = 16; off >= 1; off >>= 1) p += __shfl_xor_sync(0xffffffffu, p, off);
        if (lane == 0)
            label[((size_t)(b * CLS_ + d)) * N_ + n] = p + cb[d];
    }
}

// ---------------- host ----------------
extern "C" void kernel_launch(void* const* d_in, const int* in_sizes, int n_in,
                              void* d_out, int out_size) {
    const float* p        = (const float*)d_in[0];
    const float* x        = (const float*)d_in[1];
    const float* kp1_w    = (const float*)d_in[2];
    const float* kp2_w    = (const float*)d_in[3];
    const float* ln1_g    = (const float*)d_in[4];
    const float* ln1_b    = (const float*)d_in[5];
    const float* tdcy     = (const float*)d_in[6];
    const float* tfst     = (const float*)d_in[7];
    const float* mix_k    = (const float*)d_in[8];
    const float* mix_v    = (const float*)d_in[9];
    const float* mix_r    = (const float*)d_in[10];
    const float* att_wk   = (const float*)d_in[11];
    const float* att_wv   = (const float*)d_in[12];
    const float* att_wr   = (const float*)d_in[13];
    const float* att_wo   = (const float*)d_in[14];
    const float* ln2_g    = (const float*)d_in[15];
    const float* ln2_b    = (const float*)d_in[16];
    const float* cmix_k   = (const float*)d_in[17];
    const float* cmix_r   = (const float*)d_in[18];
    const float* ffn_wk   = (const float*)d_in[19];
    const float* ffn_wv   = (const float*)d_in[20];
    const float* ffn_wr   = (const float*)d_in[21];
    const float* bn_g     = (const float*)d_in[22];
    const float* bn_b     = (const float*)d_in[23];
    const float* conv_w   = (const float*)d_in[24];
    const float* conv_b   = (const float*)d_in[25];

    float* out_y = (float*)d_out;
    float* out_label = out_y + (size_t)B_ * C_ * N_;

    float *gf, *gx0, *gpts, *gxn, *grr, *gkT, *gvT, *gwkv, *gffn;
    cudaGetSymbolAddress((void**)&gf, g_f);
    cudaGetSymbolAddress((void**)&gx0, g_x0);
    cudaGetSymbolAddress((void**)&gpts, g_pts);
    cudaGetSymbolAddress((void**)&gxn, g_xn);
    cudaGetSymbolAddress((void**)&grr, g_rr);
    cudaGetSymbolAddress((void**)&gkT, g_kT);
    cudaGetSymbolAddress((void**)&gvT, g_vT);
    cudaGetSymbolAddress((void**)&gwkv, g_wkv);
    cudaGetSymbolAddress((void**)&gffn, g_ffn);

    __half *wak_h, *wav_h, *war_h, *wao_h, *wfk_h, *wfr_h, *wfv_h, *w1_h, *w2_h;
    cudaGetSymbolAddress((void**)&wak_h, g_wak_h);
    cudaGetSymbolAddress((void**)&wav_h, g_wav_h);
    cudaGetSymbolAddress((void**)&war_h, g_war_h);
    cudaGetSymbolAddress((void**)&wao_h, g_wao_h);
    cudaGetSymbolAddress((void**)&wfk_h, g_wfk_h);
    cudaGetSymbolAddress((void**)&wfr_h, g_wfr_h);
    cudaGetSymbolAddress((void**)&wfv_h, g_wfv_h);
    cudaGetSymbolAddress((void**)&w1_h, g_wT1_h);
    cudaGetSymbolAddress((void**)&w2_h, g_wT2_h);

    cudaFuncSetAttribute(k_mma_kpconv, cudaFuncAttributeMaxDynamicSharedMemorySize, SM_MMA);
    cudaFuncSetAttribute(k_hgemm3, cudaFuncAttributeMaxDynamicSharedMemorySize, H_SZ);

    // 1: geo setup  2: knn+prep  3: weight setup  4: build_fk
    k_setup_geo<<<33, 256>>>(p);
    k_knn_prep<<<2048, 256>>>(x);
    k_setup_w<<<1584, 256>>>(kp1_w, kp2_w, att_wk, att_wv, att_wr, att_wo,
                             ffn_wk, ffn_wr, ffn_wv);
    k_build_fk<<<M_ / 2, 128>>>(gf);
    // KPConv 1 split-K: partials in gkT/gvT, combine -> gf (f1 = fk@w1 + f0)
    k_mma_kpconv<<<dim3(M_ / 64, 2), 256, SM_MMA>>>(w1_h, gf, nullptr, gkT, gvT);
    k_add2<<<1024, 256>>>((const float4*)gkT, (const float4*)gvT, (float4*)gf);
    // KPConv 2 split-K: pts = fk@w2 + f1 + x0 (combined inside LN below)
    k_build_fk<<<M_ / 2, 128>>>(gf);
    k_mma_kpconv<<<dim3(M_ / 64, 2), 256, SM_MMA>>>(w2_h, gf, gx0, gkT, gvT);

    // ---- RWKV spatial mix (LN fuses the split-K combine; writes gpts + gxn) ----
    k_ln<<<M_, 128>>>(gkT, gvT, ln1_g, ln1_b, gpts, gxn);
    {
        HA3 qkv;
        qkv.a[0] = { wak_h, gkT, mix_k, nullptr, nullptr, 0, 1, C_ };
        qkv.a[1] = { wav_h, gvT, mix_v, nullptr, nullptr, 0, 1, C_ };
        qkv.a[2] = { war_h, grr, mix_r, nullptr, nullptr, 1, 0, C_ };
        k_hgemm3<<<dim3(128, 2, 3), 256, H_SZ>>>(gxn, qkv, C_);
    }
    k_wkv<<<32, 256>>>(gkT, gvT, grr, tdcy, tfst, gwkv);
    {
        HA3 wo;
        wo.a[0] = { wao_h, gpts, nullptr, gpts, nullptr, 0, 0, C_ };
        wo.a[1] = wo.a[0]; wo.a[2] = wo.a[0];
        k_hgemm3<<<dim3(128, 2, 1), 256, H_SZ>>>(gwkv, wo, C_);
    }

    // ---- channel mix ----
    k_ln<<<M_, 128>>>(gpts, nullptr, ln2_g, ln2_b, nullptr, gxn);
    {
        HA3 fkr;
        fkr.a[0] = { wfk_h, gffn, cmix_k, nullptr, nullptr, 2, 0, F_ };
        fkr.a[1] = { wfr_h, grr,  cmix_r, nullptr, nullptr, 1, 0, C_ };
        fkr.a[2] = fkr.a[0];
        k_hgemm3<<<dim3(128, 8, 2), 256, H_SZ>>>(gxn, fkr, C_);
    }
    {
        HA3 fv;
        fv.a[0] = { wfv_h, gpts, nullptr, gpts, grr, 0, 0, C_ };
        fv.a[1] = fv.a[0]; fv.a[2] = fv.a[0];
        k_hgemm3<<<dim3(128, 2, 1), 256, H_SZ>>>(gffn, fv, F_);
    }

    // ---- outputs (transpose + BN partials fused) ----
    k_out_tb<<<1280, 256>>>(gpts, out_y);
    k_bnred<<<1, 128>>>(bn_g, bn_b);
    k_head<<<M_ / 8, 256>>>(gpts, conv_w, conv_b, out_label);
    (void)in_sizes; (void)n_in; (void)out_size;
}